// round 1
// baseline (speedup 1.0000x reference)
#include <cuda_runtime.h>
#include <cstddef>

#define Nn   4096
#define Dd   128
#define Hh   2
#define DHd  64
#define FFd  256
#define NEe  2048
#define NNZz 65536

// ---------------- scratch (device globals; no allocations allowed) ----------
__device__ float g_h [Nn*Dd];
__device__ float g_q [Nn*Dd];
__device__ float g_k [Nn*Dd];
__device__ float g_v [Nn*Dd];
__device__ float g_ao[Nn*Dd];
__device__ float g_u [Nn*Dd];
__device__ float g_z [Nn*FFd];
__device__ float g_xt[Nn*Dd];
__device__ float g_e [NEe*Dd];
__device__ float g_bcnt[NEe];
__device__ float g_dcnt[Nn];
__device__ float g_binv[NEe];
__device__ float g_dinv[Nn];
__device__ int   g_is64;

// ---------------- copy x -> h ----------------------------------------------
__global__ void copy_kernel(const float* __restrict__ x) {
    int i = blockIdx.x * blockDim.x + threadIdx.x;
    if (i < Nn*Dd) g_h[i] = x[i];
}

// ---------------- generic tiled fp32 GEMM: C = A[MxK] * B[KxNcol] (+bias) ---
// SIG=1 applies sigmoid in epilogue. bias may be null.
template<int SIG>
__global__ __launch_bounds__(256) void gemm_kernel(
    const float* __restrict__ A, const float* __restrict__ B,
    const float* __restrict__ bias, float* __restrict__ C,
    int M, int K, int Ncol)
{
    __shared__ float As[16][68];
    __shared__ float Bs[16][64];
    const int tid = threadIdx.x;
    const int ty = tid >> 4, tx = tid & 15;
    const int m0 = blockIdx.y << 6, n0 = blockIdx.x << 6;
    const int arow = tid >> 2, aq = tid & 3;
    const int brow = tid >> 4, bq = tid & 15;

    float acc[4][4] = {};

    for (int k0 = 0; k0 < K; k0 += 16) {
        float4 av = *(const float4*)(A + (size_t)(m0 + arow) * K + k0 + (aq << 2));
        float4 bv = *(const float4*)(B + (size_t)(k0 + brow) * Ncol + n0 + (bq << 2));
        __syncthreads();
        As[(aq<<2)+0][arow] = av.x;
        As[(aq<<2)+1][arow] = av.y;
        As[(aq<<2)+2][arow] = av.z;
        As[(aq<<2)+3][arow] = av.w;
        *(float4*)(&Bs[brow][bq<<2]) = bv;
        __syncthreads();
#pragma unroll
        for (int kk = 0; kk < 16; kk++) {
            float4 a = *(const float4*)(&As[kk][ty<<2]);
            float4 b = *(const float4*)(&Bs[kk][tx<<2]);
            float aa[4] = {a.x, a.y, a.z, a.w};
            float bb[4] = {b.x, b.y, b.z, b.w};
#pragma unroll
            for (int i = 0; i < 4; i++)
#pragma unroll
                for (int j = 0; j < 4; j++)
                    acc[i][j] = fmaf(aa[i], bb[j], acc[i][j]);
        }
    }

    float bx = 0.f, by = 0.f, bz = 0.f, bw = 0.f;
    if (bias) {
        bx = bias[n0 + (tx<<2) + 0];
        by = bias[n0 + (tx<<2) + 1];
        bz = bias[n0 + (tx<<2) + 2];
        bw = bias[n0 + (tx<<2) + 3];
    }
#pragma unroll
    for (int i = 0; i < 4; i++) {
        float4 o;
        o.x = acc[i][0] + bx;
        o.y = acc[i][1] + by;
        o.z = acc[i][2] + bz;
        o.w = acc[i][3] + bw;
        if (SIG) {
            o.x = 1.f / (1.f + __expf(-o.x));
            o.y = 1.f / (1.f + __expf(-o.y));
            o.z = 1.f / (1.f + __expf(-o.z));
            o.w = 1.f / (1.f + __expf(-o.w));
        }
        *(float4*)(C + (size_t)(m0 + (ty<<2) + i) * Ncol + n0 + (tx<<2)) = o;
    }
}

// ---------------- flash attention (fp32, online softmax) --------------------
__device__ __forceinline__ float redmax16(float v) {
    v = fmaxf(v, __shfl_xor_sync(0xffffffffu, v, 8));
    v = fmaxf(v, __shfl_xor_sync(0xffffffffu, v, 4));
    v = fmaxf(v, __shfl_xor_sync(0xffffffffu, v, 2));
    v = fmaxf(v, __shfl_xor_sync(0xffffffffu, v, 1));
    return v;
}
__device__ __forceinline__ float redsum16(float v) {
    v += __shfl_xor_sync(0xffffffffu, v, 8);
    v += __shfl_xor_sync(0xffffffffu, v, 4);
    v += __shfl_xor_sync(0xffffffffu, v, 2);
    v += __shfl_xor_sync(0xffffffffu, v, 1);
    return v;
}

// grid (N/64, H), 256 threads. Q is pre-scaled by 1/sqrt(DH) at load.
__global__ __launch_bounds__(256) void flash_kernel(
    const float* __restrict__ Qp, const float* __restrict__ Kp,
    const float* __restrict__ Vp, float* __restrict__ Op)
{
    __shared__ float Qs[64][64];   // [d][row]
    __shared__ float KPs[64][64];  // K as [d][col], later reused as P [row][col]
    __shared__ float Vs[64][64];   // [col][d]

    const int tid = threadIdx.x;
    const int ty = tid >> 4, tx = tid & 15;
    const int hh = blockIdx.y;
    const int m0 = blockIdx.x << 6;
    const int lrow = tid >> 2, lq = tid & 3;

    // load + scale Q tile (transposed)
    {
        const float* qbase = Qp + (size_t)(m0 + lrow) * Dd + hh * DHd;
#pragma unroll
        for (int i = 0; i < 4; i++) {
            int d = (lq << 4) + (i << 2);
            float4 qv = *(const float4*)(qbase + d);
            Qs[d+0][lrow] = qv.x * 0.125f;
            Qs[d+1][lrow] = qv.y * 0.125f;
            Qs[d+2][lrow] = qv.z * 0.125f;
            Qs[d+3][lrow] = qv.w * 0.125f;
        }
    }

    float o[4][4] = {};
    float m_i[4], l_i[4];
#pragma unroll
    for (int i = 0; i < 4; i++) { m_i[i] = -3e38f; l_i[i] = 0.f; }

    for (int kt = 0; kt < Nn; kt += 64) {
        const float* kbase = Kp + (size_t)(kt + lrow) * Dd + hh * DHd;
        const float* vbase = Vp + (size_t)(kt + lrow) * Dd + hh * DHd;
        float4 kv[4], vv[4];
#pragma unroll
        for (int i = 0; i < 4; i++) {
            int d = (lq << 4) + (i << 2);
            kv[i] = *(const float4*)(kbase + d);
            vv[i] = *(const float4*)(vbase + d);
        }
        __syncthreads();   // previous PV reads of KPs/Vs done
#pragma unroll
        for (int i = 0; i < 4; i++) {
            int d = (lq << 4) + (i << 2);
            KPs[d+0][lrow] = kv[i].x;
            KPs[d+1][lrow] = kv[i].y;
            KPs[d+2][lrow] = kv[i].z;
            KPs[d+3][lrow] = kv[i].w;
            *(float4*)(&Vs[lrow][d]) = vv[i];
        }
        __syncthreads();

        // S = Q K^T (scaled)
        float s[4][4] = {};
#pragma unroll 16
        for (int d = 0; d < 64; d++) {
            float4 qv = *(const float4*)(&Qs[d][ty<<2]);
            float4 kk = *(const float4*)(&KPs[d][tx<<2]);
            float qa[4] = {qv.x, qv.y, qv.z, qv.w};
            float ka[4] = {kk.x, kk.y, kk.z, kk.w};
#pragma unroll
            for (int i = 0; i < 4; i++)
#pragma unroll
                for (int j = 0; j < 4; j++)
                    s[i][j] = fmaf(qa[i], ka[j], s[i][j]);
        }
        __syncthreads();   // all K reads done; KPs becomes P

        // online softmax update
        float sc[4];
#pragma unroll
        for (int i = 0; i < 4; i++) {
            float mx = fmaxf(fmaxf(s[i][0], s[i][1]), fmaxf(s[i][2], s[i][3]));
            mx = redmax16(mx);
            float mn = fmaxf(m_i[i], mx);
            sc[i] = __expf(m_i[i] - mn);
            m_i[i] = mn;
            float rs = 0.f;
#pragma unroll
            for (int j = 0; j < 4; j++) {
                float p = __expf(s[i][j] - mn);
                s[i][j] = p;
                rs += p;
            }
            rs = redsum16(rs);
            l_i[i] = l_i[i] * sc[i] + rs;
#pragma unroll
            for (int j = 0; j < 4; j++) o[i][j] *= sc[i];
        }
        // store P
#pragma unroll
        for (int i = 0; i < 4; i++)
#pragma unroll
            for (int j = 0; j < 4; j++)
                KPs[(ty<<2)+i][(tx<<2)+j] = s[i][j];
        __syncthreads();

        // O += P V
#pragma unroll 16
        for (int c = 0; c < 64; c++) {
            float4 vvv = *(const float4*)(&Vs[c][tx<<2]);
            float va[4] = {vvv.x, vvv.y, vvv.z, vvv.w};
            float p0 = KPs[(ty<<2)+0][c];
            float p1 = KPs[(ty<<2)+1][c];
            float p2 = KPs[(ty<<2)+2][c];
            float p3 = KPs[(ty<<2)+3][c];
#pragma unroll
            for (int j = 0; j < 4; j++) {
                o[0][j] = fmaf(p0, va[j], o[0][j]);
                o[1][j] = fmaf(p1, va[j], o[1][j]);
                o[2][j] = fmaf(p2, va[j], o[2][j]);
                o[3][j] = fmaf(p3, va[j], o[3][j]);
            }
        }
    }

#pragma unroll
    for (int i = 0; i < 4; i++) {
        float inv = 1.f / l_i[i];
        float4 ov;
        ov.x = o[i][0] * inv;
        ov.y = o[i][1] * inv;
        ov.z = o[i][2] * inv;
        ov.w = o[i][3] * inv;
        *(float4*)(Op + (size_t)(m0 + (ty<<2) + i) * Dd + hh * DHd + (tx<<2)) = ov;
    }
}

// ---------------- residual + LayerNorm: out = LN(h + u) ---------------------
__global__ __launch_bounds__(128) void ln_kernel(
    const float* __restrict__ h, const float* __restrict__ u,
    const float* __restrict__ g, const float* __restrict__ b,
    float* __restrict__ out)
{
    const int row = blockIdx.x, t = threadIdx.x;
    float val = h[row*Dd + t] + u[row*Dd + t];
    float s = val, s2 = val * val;
#pragma unroll
    for (int off = 16; off; off >>= 1) {
        s  += __shfl_xor_sync(0xffffffffu, s,  off);
        s2 += __shfl_xor_sync(0xffffffffu, s2, off);
    }
    __shared__ float ps[4], ps2[4];
    int w = t >> 5, lane = t & 31;
    if (lane == 0) { ps[w] = s; ps2[w] = s2; }
    __syncthreads();
    s  = ps[0] + ps[1] + ps[2] + ps[3];
    s2 = ps2[0] + ps2[1] + ps2[2] + ps2[3];
    float mean = s * (1.f / 128.f);
    float var  = s2 * (1.f / 128.f) - mean * mean;
    out[row*Dd + t] = (val - mean) * rsqrtf(var + 1e-5f) * g[t] + b[t];
}

// ---------------- hypergraph conv pieces ------------------------------------
__global__ void detect_kernel(const void* edge) {
    if (threadIdx.x == 0 && blockIdx.x == 0) {
        const int* p = (const int*)edge;
        int is64 = 1;
        for (int i = 0; i < 64; i++)
            if (p[2*i + 1] != 0) { is64 = 0; break; }
        g_is64 = is64;
    }
}

__device__ __forceinline__ int eidx(const void* e, int i, int is64) {
    if (is64) return (int)((const long long*)e)[i];
    return ((const int*)e)[i];
}

__global__ void zero_kernel(float* out) {
    int i = blockIdx.x * blockDim.x + threadIdx.x;
    if (i < NEe*Dd) g_e[i] = 0.f;
    if (i < NEe)    g_bcnt[i] = 0.f;
    if (i < Nn)     g_dcnt[i] = 0.f;
    if (i < Nn*Dd)  out[i] = 0.f;
}

__global__ void count_kernel(const void* edge) {
    int j = blockIdx.x * blockDim.x + threadIdx.x;
    if (j >= NNZz) return;
    int is64 = g_is64;
    int node = eidx(edge, j, is64);
    int he   = eidx(edge, NNZz + j, is64);
    atomicAdd(&g_dcnt[node], 1.f);
    atomicAdd(&g_bcnt[he],   1.f);
}

__global__ void inv_kernel() {
    int i = blockIdx.x * blockDim.x + threadIdx.x;
    if (i < NEe) { float c = g_bcnt[i]; g_binv[i] = (c > 0.f) ? 1.f / c : 0.f; }
    if (i < Nn)  { float c = g_dcnt[i]; g_dinv[i] = (c > 0.f) ? 1.f / c : 0.f; }
}

// e[he] += xt[node]   (per-thread: one nz, 4 consecutive floats)
__global__ void scatter_e_kernel(const void* edge) {
    int gid = blockIdx.x * blockDim.x + threadIdx.x;
    if (gid >= NNZz * 32) return;
    int j = gid >> 5;
    int dq = (gid & 31) << 2;
    int is64 = g_is64;
    int node = eidx(edge, j, is64);
    int he   = eidx(edge, NNZz + j, is64);
    float4 xv = *(const float4*)(&g_xt[node*Dd + dq]);
    float* ep = &g_e[he*Dd + dq];
    atomicAdd(ep + 0, xv.x);
    atomicAdd(ep + 1, xv.y);
    atomicAdd(ep + 2, xv.z);
    atomicAdd(ep + 3, xv.w);
}

// out[node] += e[he] * Binv[he]
__global__ void scatter_out_kernel(const void* edge, float* __restrict__ out) {
    int gid = blockIdx.x * blockDim.x + threadIdx.x;
    if (gid >= NNZz * 32) return;
    int j = gid >> 5;
    int dq = (gid & 31) << 2;
    int is64 = g_is64;
    int node = eidx(edge, j, is64);
    int he   = eidx(edge, NNZz + j, is64);
    float bi = g_binv[he];
    float4 ev = *(const float4*)(&g_e[he*Dd + dq]);
    float* op = &out[node*Dd + dq];
    atomicAdd(op + 0, ev.x * bi);
    atomicAdd(op + 1, ev.y * bi);
    atomicAdd(op + 2, ev.z * bi);
    atomicAdd(op + 3, ev.w * bi);
}

__global__ void final_kernel(float* __restrict__ out, const float* __restrict__ bh) {
    int i = blockIdx.x * blockDim.x + threadIdx.x;
    if (i >= Nn*Dd) return;
    float v = out[i] * g_dinv[i >> 7] + bh[i & 127];
    out[i] = v > 0.f ? v : 0.f;
}

// ---------------- launch ----------------------------------------------------
extern "C" void kernel_launch(void* const* d_in, const int* in_sizes, int n_in,
                              void* d_out, int out_size)
{
    const float* x    = (const float*)d_in[0];
    const void*  edge = d_in[1];
    const float* Wq = (const float*)d_in[2];
    const float* bq = (const float*)d_in[3];
    const float* Wk = (const float*)d_in[4];
    const float* bk = (const float*)d_in[5];
    const float* Wv = (const float*)d_in[6];
    const float* bv = (const float*)d_in[7];
    const float* Wo = (const float*)d_in[8];
    const float* bo = (const float*)d_in[9];
    const float* g1 = (const float*)d_in[10];
    const float* b1 = (const float*)d_in[11];
    const float* W1 = (const float*)d_in[12];
    const float* bf1= (const float*)d_in[13];
    const float* W2 = (const float*)d_in[14];
    const float* bf2= (const float*)d_in[15];
    const float* g2 = (const float*)d_in[16];
    const float* b2 = (const float*)d_in[17];
    const float* Wh = (const float*)d_in[18];
    const float* bh = (const float*)d_in[19];
    float* out = (float*)d_out;

    static float *p_h=nullptr, *p_q, *p_k, *p_v, *p_ao, *p_u, *p_z, *p_xt;
    if (!p_h) {
        cudaGetSymbolAddress((void**)&p_h,  g_h);
        cudaGetSymbolAddress((void**)&p_q,  g_q);
        cudaGetSymbolAddress((void**)&p_k,  g_k);
        cudaGetSymbolAddress((void**)&p_v,  g_v);
        cudaGetSymbolAddress((void**)&p_ao, g_ao);
        cudaGetSymbolAddress((void**)&p_u,  g_u);
        cudaGetSymbolAddress((void**)&p_z,  g_z);
        cudaGetSymbolAddress((void**)&p_xt, g_xt);
    }

    copy_kernel<<<(Nn*Dd + 255)/256, 256>>>(x);

    const dim3 gD(Dd/64, Nn/64);    // 128-col outputs
    const dim3 gF(FFd/64, Nn/64);   // 256-col outputs
    const dim3 gA(Nn/64, Hh);       // flash attention

    for (int layer = 0; layer < 2; layer++) {
        gemm_kernel<0><<<gD, 256>>>(p_h, Wq, bq, p_q, Nn, Dd, Dd);
        gemm_kernel<0><<<gD, 256>>>(p_h, Wk, bk, p_k, Nn, Dd, Dd);
        gemm_kernel<0><<<gD, 256>>>(p_h, Wv, bv, p_v, Nn, Dd, Dd);
        flash_kernel<<<gA, 256>>>(p_q, p_k, p_v, p_ao);
        gemm_kernel<0><<<gD, 256>>>(p_ao, Wo, bo, p_u, Nn, Dd, Dd);
        ln_kernel<<<Nn, 128>>>(p_h, p_u, g1, b1, p_h);
        gemm_kernel<1><<<gF, 256>>>(p_h, W1, bf1, p_z, Nn, Dd, FFd);
        gemm_kernel<0><<<gD, 256>>>(p_z, W2, bf2, p_u, Nn, FFd, Dd);
        ln_kernel<<<Nn, 128>>>(p_h, p_u, g2, b2, p_h);
    }

    gemm_kernel<0><<<gD, 256>>>(p_h, Wh, (const float*)nullptr, p_xt, Nn, Dd, Dd);

    detect_kernel<<<1, 32>>>(edge);
    zero_kernel<<<(Nn*Dd + 255)/256, 256>>>(out);
    count_kernel<<<(NNZz + 255)/256, 256>>>(edge);
    inv_kernel<<<(Nn + 255)/256, 256>>>();
    scatter_e_kernel<<<(NNZz*32 + 255)/256, 256>>>(edge);
    scatter_out_kernel<<<(NNZz*32 + 255)/256, 256>>>(edge, out);
    final_kernel<<<(Nn*Dd + 255)/256, 256>>>(out, bh);
}

// round 11
// speedup vs baseline: 2.0811x; 2.0811x over previous
#include <cuda_runtime.h>
#include <cstdint>
#include <cstddef>

#define Nn   4096
#define Dd   128
#define Hh   2
#define DHd  64
#define FFd  256
#define NEe  2048
#define NNZz 65536
#define S72  72

// ---------------- scratch (device globals) ----------------------------------
__device__ float g_h [Nn*Dd];
__device__ float g_q [Nn*Dd];
__device__ float g_k [Nn*Dd];
__device__ float g_v [Nn*Dd];
__device__ float g_ao[Nn*Dd];
__device__ float g_u [Nn*Dd];
__device__ float g_z [Nn*FFd];
__device__ float g_xt[Nn*Dd];
__device__ float g_e [NEe*Dd];
__device__ float g_bcnt[NEe];
__device__ float g_dcnt[Nn];
__device__ float g_binv[NEe];
__device__ float g_dinv[Nn];
__device__ int   g_is64;

// ---------------- helpers ----------------------------------------------------
__device__ __forceinline__ float tf32r(float f) {
    uint32_t u;
    asm("cvt.rna.tf32.f32 %0, %1;" : "=r"(u) : "f"(f));
    return __uint_as_float(u);
}
__device__ __forceinline__ uint32_t fbits(float f) { return __float_as_uint(f); }

__device__ __forceinline__ void mma8(float* d, const uint32_t* a, uint32_t b0, uint32_t b1) {
    asm volatile(
        "mma.sync.aligned.m16n8k8.row.col.f32.tf32.tf32.f32 "
        "{%0,%1,%2,%3},{%4,%5,%6,%7},{%8,%9},{%0,%1,%2,%3};"
        : "+f"(d[0]), "+f"(d[1]), "+f"(d[2]), "+f"(d[3])
        : "r"(a[0]), "r"(a[1]), "r"(a[2]), "r"(a[3]), "r"(b0), "r"(b1));
}

// ---------------- copy x -> h ------------------------------------------------
__global__ void copy_kernel(const float* __restrict__ x) {
    int i = blockIdx.x * blockDim.x + threadIdx.x;
    if (i < Nn*Dd) g_h[i] = x[i];
}

// ---------------- tf32 mma GEMM: C = A[MxK] * B[KxN] (+bias, opt sigmoid) ---
template<int SIG>
__global__ __launch_bounds__(128) void gemm_mma(
    const float* __restrict__ A, const float* __restrict__ B,
    const float* __restrict__ bias, float* __restrict__ C,
    int M, int K, int Ncol)
{
    __shared__ float As[64*36];
    __shared__ float Bs[32*S72];
    const int tid  = threadIdx.x;
    const int warp = tid >> 5, lane = tid & 31;
    const int gid  = lane >> 2, tig = lane & 3;
    const int wm   = warp << 4;
    const int m0 = blockIdx.y << 6, n0 = blockIdx.x << 6;

    float acc[8][4] = {};

    for (int k0 = 0; k0 < K; k0 += 32) {
        __syncthreads();
#pragma unroll
        for (int p = 0; p < 4; p++) {
            int idx = tid + p*128;
            // A tile: 64 rows x 32 k
            {
                int r = idx >> 3, c = (idx & 7) << 2;
                float4 av = *(const float4*)(A + (size_t)(m0 + r)*K + k0 + c);
                float* d = &As[r*36 + c];
                d[0] = tf32r(av.x); d[1] = tf32r(av.y);
                d[2] = tf32r(av.z); d[3] = tf32r(av.w);
            }
            // B tile: 32 k x 64 n
            {
                int r = idx >> 4, c = (idx & 15) << 2;
                float4 bv = *(const float4*)(B + (size_t)(k0 + r)*Ncol + n0 + c);
                float* d = &Bs[r*S72 + c];
                d[0] = tf32r(bv.x); d[1] = tf32r(bv.y);
                d[2] = tf32r(bv.z); d[3] = tf32r(bv.w);
            }
        }
        __syncthreads();
#pragma unroll
        for (int kk = 0; kk < 4; kk++) {
            uint32_t a[4];
            a[0] = fbits(As[(wm+gid  )*36 + kk*8 + tig    ]);
            a[1] = fbits(As[(wm+gid+8)*36 + kk*8 + tig    ]);
            a[2] = fbits(As[(wm+gid  )*36 + kk*8 + tig + 4]);
            a[3] = fbits(As[(wm+gid+8)*36 + kk*8 + tig + 4]);
#pragma unroll
            for (int j = 0; j < 8; j++) {
                uint32_t b0 = fbits(Bs[(kk*8+tig  )*S72 + j*8 + gid]);
                uint32_t b1 = fbits(Bs[(kk*8+tig+4)*S72 + j*8 + gid]);
                mma8(acc[j], a, b0, b1);
            }
        }
    }

    const int r0 = m0 + wm + gid;
#pragma unroll
    for (int j = 0; j < 8; j++) {
        int c0 = n0 + j*8 + 2*tig;
        float bx = bias ? bias[c0]   : 0.f;
        float by = bias ? bias[c0+1] : 0.f;
        float v0 = acc[j][0] + bx, v1 = acc[j][1] + by;
        float v2 = acc[j][2] + bx, v3 = acc[j][3] + by;
        if (SIG) {
            v0 = 1.f/(1.f+__expf(-v0)); v1 = 1.f/(1.f+__expf(-v1));
            v2 = 1.f/(1.f+__expf(-v2)); v3 = 1.f/(1.f+__expf(-v3));
        }
        *(float2*)(C + (size_t)r0    *Ncol + c0) = make_float2(v0, v1);
        *(float2*)(C + (size_t)(r0+8)*Ncol + c0) = make_float2(v2, v3);
    }
}

// ---------------- flash attention, tf32 mma ----------------------------------
// grid (N/64, H), 128 threads (4 warps), warp computes 16 rows.
// K and V both staged in NATURAL [key][d] layout (B-fragment reads directly).
__global__ __launch_bounds__(128) void flashm_kernel(
    const float* __restrict__ Qp, const float* __restrict__ Kp,
    const float* __restrict__ Vp, float* __restrict__ Op)
{
    extern __shared__ float sm[];
    float* Ps = sm;                // Q staging, later P tiles (warp-local rows)
    float* Ks = sm + 64*S72;       // K [key][d]
    float* Vs = sm + 2*64*S72;     // V [key][d]

    const int tid  = threadIdx.x;
    const int warp = tid >> 5, lane = tid & 31;
    const int gid  = lane >> 2, tig = lane & 3;
    const int wm   = warp << 4;
    const int hh = blockIdx.y;
    const int m0 = blockIdx.x << 6;

    // stage Q (pre-scaled by 1/sqrt(64), tf32-rounded)
#pragma unroll
    for (int p = 0; p < 8; p++) {
        int idx = tid + p*128;
        int r = idx >> 4, c = (idx & 15) << 2;
        float4 qv = *(const float4*)(Qp + (size_t)(m0 + r)*Dd + hh*DHd + c);
        float* d = &Ps[r*S72 + c];
        d[0] = tf32r(qv.x * 0.125f); d[1] = tf32r(qv.y * 0.125f);
        d[2] = tf32r(qv.z * 0.125f); d[3] = tf32r(qv.w * 0.125f);
    }
    __syncthreads();

    uint32_t qa[8][4];
#pragma unroll
    for (int kk = 0; kk < 8; kk++) {
        qa[kk][0] = fbits(Ps[(wm+gid  )*S72 + kk*8 + tig    ]);
        qa[kk][1] = fbits(Ps[(wm+gid+8)*S72 + kk*8 + tig    ]);
        qa[kk][2] = fbits(Ps[(wm+gid  )*S72 + kk*8 + tig + 4]);
        qa[kk][3] = fbits(Ps[(wm+gid+8)*S72 + kk*8 + tig + 4]);
    }

    float o[8][4] = {};
    float mr0 = -3e38f, mr1 = -3e38f, l0 = 0.f, l1 = 0.f;

    for (int kt = 0; kt < Nn; kt += 64) {
        __syncthreads();   // prior tile's reads of Ks/Vs complete
#pragma unroll
        for (int p = 0; p < 8; p++) {
            int idx = tid + p*128;
            int r = idx >> 4, c = (idx & 15) << 2;
            float4 kv = *(const float4*)(Kp + (size_t)(kt + r)*Dd + hh*DHd + c);
            float* dk = &Ks[r*S72 + c];
            dk[0] = tf32r(kv.x); dk[1] = tf32r(kv.y);
            dk[2] = tf32r(kv.z); dk[3] = tf32r(kv.w);
            float4 vv = *(const float4*)(Vp + (size_t)(kt + r)*Dd + hh*DHd + c);
            float* dv = &Vs[r*S72 + c];
            dv[0] = tf32r(vv.x); dv[1] = tf32r(vv.y);
            dv[2] = tf32r(vv.z); dv[3] = tf32r(vv.w);
        }
        __syncthreads();

        // S = Q K^T  (16 x 64 per warp); B(k=d, n=key) = Ks[key][d]
        float s[8][4] = {};
#pragma unroll
        for (int kk = 0; kk < 8; kk++) {
#pragma unroll
            for (int j = 0; j < 8; j++) {
                uint32_t b0 = fbits(Ks[(j*8+gid)*S72 + kk*8 + tig    ]);
                uint32_t b1 = fbits(Ks[(j*8+gid)*S72 + kk*8 + tig + 4]);
                mma8(s[j], qa[kk], b0, b1);
            }
        }

        // online softmax (rows wm+gid and wm+gid+8)
        float mx0 = -3e38f, mx1 = -3e38f;
#pragma unroll
        for (int j = 0; j < 8; j++) {
            mx0 = fmaxf(mx0, fmaxf(s[j][0], s[j][1]));
            mx1 = fmaxf(mx1, fmaxf(s[j][2], s[j][3]));
        }
        mx0 = fmaxf(mx0, __shfl_xor_sync(0xffffffffu, mx0, 1));
        mx0 = fmaxf(mx0, __shfl_xor_sync(0xffffffffu, mx0, 2));
        mx1 = fmaxf(mx1, __shfl_xor_sync(0xffffffffu, mx1, 1));
        mx1 = fmaxf(mx1, __shfl_xor_sync(0xffffffffu, mx1, 2));
        float nm0 = fmaxf(mr0, mx0), nm1 = fmaxf(mr1, mx1);
        float sc0 = __expf(mr0 - nm0), sc1 = __expf(mr1 - nm1);
        mr0 = nm0; mr1 = nm1;
        float sum0 = 0.f, sum1 = 0.f;
#pragma unroll
        for (int j = 0; j < 8; j++) {
            float p0 = __expf(s[j][0] - nm0);
            float p1 = __expf(s[j][1] - nm0);
            float p2 = __expf(s[j][2] - nm1);
            float p3 = __expf(s[j][3] - nm1);
            sum0 += p0 + p1; sum1 += p2 + p3;
            s[j][0] = p0; s[j][1] = p1; s[j][2] = p2; s[j][3] = p3;
            o[j][0] *= sc0; o[j][1] *= sc0; o[j][2] *= sc1; o[j][3] *= sc1;
        }
        sum0 += __shfl_xor_sync(0xffffffffu, sum0, 1);
        sum0 += __shfl_xor_sync(0xffffffffu, sum0, 2);
        sum1 += __shfl_xor_sync(0xffffffffu, sum1, 1);
        sum1 += __shfl_xor_sync(0xffffffffu, sum1, 2);
        l0 = l0*sc0 + sum0;
        l1 = l1*sc1 + sum1;

        // store P (warp-local rows of Ps)
#pragma unroll
        for (int j = 0; j < 8; j++) {
            Ps[(wm+gid  )*S72 + j*8 + 2*tig    ] = tf32r(s[j][0]);
            Ps[(wm+gid  )*S72 + j*8 + 2*tig + 1] = tf32r(s[j][1]);
            Ps[(wm+gid+8)*S72 + j*8 + 2*tig    ] = tf32r(s[j][2]);
            Ps[(wm+gid+8)*S72 + j*8 + 2*tig + 1] = tf32r(s[j][3]);
        }
        __syncwarp();

        // O += P V ; B(k=key, n=d) = Vs[key][d]
#pragma unroll
        for (int kk = 0; kk < 8; kk++) {
            uint32_t pa[4];
            pa[0] = fbits(Ps[(wm+gid  )*S72 + kk*8 + tig    ]);
            pa[1] = fbits(Ps[(wm+gid+8)*S72 + kk*8 + tig    ]);
            pa[2] = fbits(Ps[(wm+gid  )*S72 + kk*8 + tig + 4]);
            pa[3] = fbits(Ps[(wm+gid+8)*S72 + kk*8 + tig + 4]);
#pragma unroll
            for (int j = 0; j < 8; j++) {
                uint32_t b0 = fbits(Vs[(kk*8+tig  )*S72 + j*8 + gid]);
                uint32_t b1 = fbits(Vs[(kk*8+tig+4)*S72 + j*8 + gid]);
                mma8(o[j], pa, b0, b1);
            }
        }
        __syncwarp();   // PV reads of Ps done before next tile's P store
    }

    float i0 = 1.f / l0, i1 = 1.f / l1;
    const int r0 = m0 + wm + gid;
#pragma unroll
    for (int j = 0; j < 8; j++) {
        int c0 = hh*DHd + j*8 + 2*tig;
        *(float2*)(Op + (size_t)r0    *Dd + c0) = make_float2(o[j][0]*i0, o[j][1]*i0);
        *(float2*)(Op + (size_t)(r0+8)*Dd + c0) = make_float2(o[j][2]*i1, o[j][3]*i1);
    }
}

// ---------------- residual + LayerNorm ---------------------------------------
__global__ __launch_bounds__(128) void ln_kernel(
    const float* __restrict__ h, const float* __restrict__ u,
    const float* __restrict__ g, const float* __restrict__ b,
    float* __restrict__ out)
{
    const int row = blockIdx.x, t = threadIdx.x;
    float val = h[row*Dd + t] + u[row*Dd + t];
    float s = val, s2 = val * val;
#pragma unroll
    for (int off = 16; off; off >>= 1) {
        s  += __shfl_xor_sync(0xffffffffu, s,  off);
        s2 += __shfl_xor_sync(0xffffffffu, s2, off);
    }
    __shared__ float ps[4], ps2[4];
    int w = t >> 5, lane = t & 31;
    if (lane == 0) { ps[w] = s; ps2[w] = s2; }
    __syncthreads();
    s  = ps[0] + ps[1] + ps[2] + ps[3];
    s2 = ps2[0] + ps2[1] + ps2[2] + ps2[3];
    float mean = s * (1.f / 128.f);
    float var  = s2 * (1.f / 128.f) - mean * mean;
    out[row*Dd + t] = (val - mean) * rsqrtf(var + 1e-5f) * g[t] + b[t];
}

// ---------------- hypergraph conv --------------------------------------------
__global__ void detect_kernel(const void* edge) {
    if (threadIdx.x == 0 && blockIdx.x == 0) {
        const int* p = (const int*)edge;
        int is64 = 1;
        for (int i = 0; i < 64; i++)
            if (p[2*i + 1] != 0) { is64 = 0; break; }
        g_is64 = is64;
    }
}

__device__ __forceinline__ int eidx(const void* e, int i, int is64) {
    if (is64) return (int)((const long long*)e)[i];
    return ((const int*)e)[i];
}

__global__ void zero_kernel(float* out) {
    int i = blockIdx.x * blockDim.x + threadIdx.x;
    if (i < NEe*Dd) g_e[i] = 0.f;
    if (i < NEe)    g_bcnt[i] = 0.f;
    if (i < Nn)     g_dcnt[i] = 0.f;
    if (i < Nn*Dd)  out[i] = 0.f;
}

__global__ void count_kernel(const void* edge) {
    int j = blockIdx.x * blockDim.x + threadIdx.x;
    if (j >= NNZz) return;
    int is64 = g_is64;
    atomicAdd(&g_dcnt[eidx(edge, j, is64)], 1.f);
    atomicAdd(&g_bcnt[eidx(edge, NNZz + j, is64)], 1.f);
}

__global__ void inv_kernel() {
    int i = blockIdx.x * blockDim.x + threadIdx.x;
    if (i < NEe) { float c = g_bcnt[i]; g_binv[i] = (c > 0.f) ? 1.f / c : 0.f; }
    if (i < Nn)  { float c = g_dcnt[i]; g_dinv[i] = (c > 0.f) ? 1.f / c : 0.f; }
}

__global__ void scatter_e_kernel(const void* edge) {
    int gid = blockIdx.x * blockDim.x + threadIdx.x;
    if (gid >= NNZz * 32) return;
    int j = gid >> 5;
    int dq = (gid & 31) << 2;
    int is64 = g_is64;
    int node = eidx(edge, j, is64);
    int he   = eidx(edge, NNZz + j, is64);
    float4 xv = *(const float4*)(&g_xt[node*Dd + dq]);
    float* ep = &g_e[he*Dd + dq];
    atomicAdd(ep + 0, xv.x);
    atomicAdd(ep + 1, xv.y);
    atomicAdd(ep + 2, xv.z);
    atomicAdd(ep + 3, xv.w);
}

__global__ void scatter_out_kernel(const void* edge, float* __restrict__ out) {
    int gid = blockIdx.x * blockDim.x + threadIdx.x;
    if (gid >= NNZz * 32) return;
    int j = gid >> 5;
    int dq = (gid & 31) << 2;
    int is64 = g_is64;
    int node = eidx(edge, j, is64);
    int he   = eidx(edge, NNZz + j, is64);
    float bi = g_binv[he];
    float4 ev = *(const float4*)(&g_e[he*Dd + dq]);
    float* op = &out[node*Dd + dq];
    atomicAdd(op + 0, ev.x * bi);
    atomicAdd(op + 1, ev.y * bi);
    atomicAdd(op + 2, ev.z * bi);
    atomicAdd(op + 3, ev.w * bi);
}

__global__ void final_kernel(float* __restrict__ out, const float* __restrict__ bh) {
    int i = blockIdx.x * blockDim.x + threadIdx.x;
    if (i >= Nn*Dd) return;
    float v = out[i] * g_dinv[i >> 7] + bh[i & 127];
    out[i] = v > 0.f ? v : 0.f;
}

// ---------------- launch -----------------------------------------------------
extern "C" void kernel_launch(void* const* d_in, const int* in_sizes, int n_in,
                              void* d_out, int out_size)
{
    const float* x    = (const float*)d_in[0];
    const void*  edge = d_in[1];
    const float* Wq = (const float*)d_in[2];
    const float* bq = (const float*)d_in[3];
    const float* Wk = (const float*)d_in[4];
    const float* bk = (const float*)d_in[5];
    const float* Wv = (const float*)d_in[6];
    const float* bv = (const float*)d_in[7];
    const float* Wo = (const float*)d_in[8];
    const float* bo = (const float*)d_in[9];
    const float* g1 = (const float*)d_in[10];
    const float* b1 = (const float*)d_in[11];
    const float* W1 = (const float*)d_in[12];
    const float* bf1= (const float*)d_in[13];
    const float* W2 = (const float*)d_in[14];
    const float* bf2= (const float*)d_in[15];
    const float* g2 = (const float*)d_in[16];
    const float* b2 = (const float*)d_in[17];
    const float* Wh = (const float*)d_in[18];
    const float* bh = (const float*)d_in[19];
    float* out = (float*)d_out;

    static float *p_h=nullptr, *p_q, *p_k, *p_v, *p_ao, *p_u, *p_z, *p_xt;
    if (!p_h) {
        cudaGetSymbolAddress((void**)&p_h,  g_h);
        cudaGetSymbolAddress((void**)&p_q,  g_q);
        cudaGetSymbolAddress((void**)&p_k,  g_k);
        cudaGetSymbolAddress((void**)&p_v,  g_v);
        cudaGetSymbolAddress((void**)&p_ao, g_ao);
        cudaGetSymbolAddress((void**)&p_u,  g_u);
        cudaGetSymbolAddress((void**)&p_z,  g_z);
        cudaGetSymbolAddress((void**)&p_xt, g_xt);
    }

    const int flash_smem = 3 * 64 * S72 * sizeof(float);
    cudaFuncSetAttribute(flashm_kernel,
                         cudaFuncAttributeMaxDynamicSharedMemorySize, flash_smem);

    copy_kernel<<<(Nn*Dd + 255)/256, 256>>>(x);

    const dim3 gD(Dd/64, Nn/64);    // 128-col outputs
    const dim3 gF(FFd/64, Nn/64);   // 256-col outputs
    const dim3 gA(Nn/64, Hh);

    for (int layer = 0; layer < 2; layer++) {
        gemm_mma<0><<<gD, 128>>>(p_h, Wq, bq, p_q, Nn, Dd, Dd);
        gemm_mma<0><<<gD, 128>>>(p_h, Wk, bk, p_k, Nn, Dd, Dd);
        gemm_mma<0><<<gD, 128>>>(p_h, Wv, bv, p_v, Nn, Dd, Dd);
        flashm_kernel<<<gA, 128, flash_smem>>>(p_q, p_k, p_v, p_ao);
        gemm_mma<0><<<gD, 128>>>(p_ao, Wo, bo, p_u, Nn, Dd, Dd);
        ln_kernel<<<Nn, 128>>>(p_h, p_u, g1, b1, p_h);
        gemm_mma<1><<<gF, 128>>>(p_h, W1, bf1, p_z, Nn, Dd, FFd);
        gemm_mma<0><<<gD, 128>>>(p_z, W2, bf2, p_u, Nn, FFd, Dd);
        ln_kernel<<<Nn, 128>>>(p_h, p_u, g2, b2, p_h);
    }

    gemm_mma<0><<<gD, 128>>>(p_h, Wh, (const float*)nullptr, p_xt, Nn, Dd, Dd);

    detect_kernel<<<1, 32>>>(edge);
    zero_kernel<<<(Nn*Dd + 255)/256, 256>>>(out);
    count_kernel<<<(NNZz + 255)/256, 256>>>(edge);
    inv_kernel<<<(Nn + 255)/256, 256>>>();
    scatter_e_kernel<<<(NNZz*32 + 255)/256, 256>>>(edge);
    scatter_out_kernel<<<(NNZz*32 + 255)/256, 256>>>(edge, out);
    final_kernel<<<(Nn*Dd + 255)/256, 256>>>(out, bh);
}